// round 7
// baseline (speedup 1.0000x reference)
#include <cuda_runtime.h>
#include <cuda_bf16.h>
#include <cstdint>

// ---------------- problem constants ----------------
#define DD 512
#define MAXB 32768
#define NSPLIT 16
#define BKT 128                         // K per stage (int8 elems) -> 128B rows
#define MT 128
#define NT 64
#define TILE_A (MT * BKT)               // 16384 B
#define TILE_BB (NT * BKT)              // 8192 B
#define STAGE_B (2 * TILE_A + 2 * TILE_BB)  // 49152 B
#define SMEM_DYN (2 * STAGE_B + 128)        // 98432 B -> 2 CTAs/SM

// int8 digit scale: x ~= S*(d0 + d1/128), S = 8/127
#define QS   (8.0f / 127.0f)
#define QINV 15.875f                    // 127/8
#define S2   (QS * QS)
#define S2B  (QS * QS / 128.0f)

// ---------------- scratch (device globals; no allocation) ----------------
__device__ __align__(256) int8_t g_s0[(size_t)MAXB * DD];
__device__ __align__(256) int8_t g_s1[(size_t)MAXB * DD];
__device__ __align__(256) int8_t g_p0[(size_t)MAXB * DD];
__device__ __align__(256) int8_t g_p1[(size_t)MAXB * DD];
__device__ __align__(256) int8_t g_st0[(size_t)DD * MAXB];
__device__ __align__(256) int8_t g_st1[(size_t)DD * MAXB];
__device__ __align__(256) int8_t g_pt0[(size_t)DD * MAXB];
__device__ __align__(256) int8_t g_pt1[(size_t)DD * MAXB];
__device__ __align__(256) int8_t g_wt0[DD * DD];
__device__ __align__(256) int8_t g_wt1[DD * DD];
__device__ __align__(256) int8_t g_wrt0[DD * DD];
__device__ __align__(256) int8_t g_wrt1[DD * DD];
__device__ __align__(256) float g_stim_out[(size_t)MAXB * DD];
__device__ __align__(256) float g_rec_out[(size_t)MAXB * DD];
__device__ __align__(256) float g_partS[(size_t)NSPLIT * DD * DD];
__device__ __align__(256) float g_partP[(size_t)NSPLIT * DD * DD];
__device__ __align__(256) float g_GS[DD * DD];
__device__ __align__(256) float g_GP[DD * DD];

// ---------------- PTX helpers ----------------
__device__ __forceinline__ uint32_t smem_u32(const void* p) {
    uint32_t a;
    asm("{ .reg .u64 t; cvta.to.shared.u64 t, %1; cvt.u32.u64 %0, t; }" : "=r"(a) : "l"(p));
    return a;
}
__device__ __forceinline__ void ldsm_x4(uint32_t* r, uint32_t addr) {
    asm volatile("ldmatrix.sync.aligned.m8n8.x4.shared.b16 {%0,%1,%2,%3}, [%4];"
                 : "=r"(r[0]), "=r"(r[1]), "=r"(r[2]), "=r"(r[3]) : "r"(addr));
}
__device__ __forceinline__ void imma16832(int* c, const uint32_t* a, uint32_t b0, uint32_t b1) {
    asm volatile(
        "mma.sync.aligned.m16n8k32.row.col.s32.s8.s8.s32 "
        "{%0,%1,%2,%3}, {%4,%5,%6,%7}, {%8,%9}, {%0,%1,%2,%3};"
        : "+r"(c[0]), "+r"(c[1]), "+r"(c[2]), "+r"(c[3])
        : "r"(a[0]), "r"(a[1]), "r"(a[2]), "r"(a[3]), "r"(b0), "r"(b1));
}
__device__ __forceinline__ void cp16(uint32_t dst, const void* src) {
    asm volatile("cp.async.cg.shared.global [%0], [%1], 16;" :: "r"(dst), "l"(src) : "memory");
}
#define CP_COMMIT() asm volatile("cp.async.commit_group;" ::: "memory")

// swizzled smem byte offset within a tile: 128B rows, 8 x 16B chunks, chunk xor (row&7)
__device__ __forceinline__ uint32_t swz(int row, int chunk) {
    return (uint32_t)(row * 128 + ((chunk ^ (row & 7)) << 4));
}

__device__ __forceinline__ void quant2(float v, int8_t& d0, int8_t& d1) {
    float q = fminf(fmaxf(v * QINV, -126.5f), 126.5f);
    int i0 = __float2int_rn(q);
    int i1 = __float2int_rn((q - (float)i0) * 128.f);
    d0 = (int8_t)i0;
    d1 = (int8_t)i1;
}

// ---------------- segment descriptor for the merged GEMM launch ----------------
struct Seg {
    const int8_t *A0, *A1, *B0, *B1;
    long lda, ldb;
    float* C;
    long pstride;
    int kc;     // K per block (int8 elements)
    int gram;   // 0: forward tiling, 1: upper-tri gram tiling
    int blk0;
};
struct Seg4 { Seg s[4]; };

// ---------------- stage loader: A0(128), A1(128), B0(64), B1(64) rows of 128B ----------------
__device__ __forceinline__ void load_stage(uint32_t sb,
                                           const int8_t* __restrict__ A0, const int8_t* __restrict__ A1,
                                           const int8_t* __restrict__ B0, const int8_t* __restrict__ B1,
                                           long lda, long ldb, long m0, long n0, long k0, int tid) {
    const int8_t* pA0 = A0 + m0 * lda + k0;
    const int8_t* pA1 = A1 + m0 * lda + k0;
    const int8_t* pB0 = B0 + n0 * ldb + k0;
    const int8_t* pB1 = B1 + n0 * ldb + k0;
#pragma unroll
    for (int q = 0; q < 4; ++q) {
        int ci = tid + q * 256;
        int row = ci >> 3, c = ci & 7;
        cp16(sb + swz(row, c), pA0 + (long)row * lda + c * 16);
    }
#pragma unroll
    for (int q = 0; q < 4; ++q) {
        int ci = tid + q * 256;
        int row = ci >> 3, c = ci & 7;
        cp16(sb + TILE_A + swz(row, c), pA1 + (long)row * lda + c * 16);
    }
#pragma unroll
    for (int q = 0; q < 2; ++q) {
        int ci = tid + q * 256;
        int row = ci >> 3, c = ci & 7;
        cp16(sb + 2 * TILE_A + swz(row, c), pB0 + (long)row * ldb + c * 16);
    }
#pragma unroll
    for (int q = 0; q < 2; ++q) {
        int ci = tid + q * 256;
        int row = ci >> 3, c = ci & 7;
        cp16(sb + 2 * TILE_A + TILE_BB + swz(row, c), pB1 + (long)row * ldb + c * 16);
    }
    CP_COMMIT();
}

// ---------------- merged int8 IMMA GEMM: all 4 GEMMs in one launch ----------------
__global__ __launch_bounds__(256, 2)
void mma_all(Seg4 segs) {
    extern __shared__ char smraw[];
    const uint32_t base = (smem_u32(smraw) + 127u) & ~127u;

    const int bid = blockIdx.x;
    int si = (bid >= segs.s[2].blk0) ? ((bid >= segs.s[3].blk0) ? 3 : 2)
                                     : ((bid >= segs.s[1].blk0) ? 1 : 0);
    const Seg sg = segs.s[si];
    const int b = bid - sg.blk0;

    const int tid = threadIdx.x;
    const int lane = tid & 31;
    const int wid = tid >> 5;
    const int wm = wid >> 1;       // 4 warp-rows of 32
    const int wn = wid & 1;        // 2 warp-cols of 32
    const int r15 = lane & 15;
    const int hi4 = lane >> 4;

    long m0, n0, kbase;
    float* C = sg.C;
    if (sg.gram) {
        const int PI[20] = {0,0, 0,0, 0,0, 0,0, 1,1, 1,1, 1,1, 2,2, 2,2, 3,3};
        const int PN[20] = {0,1, 2,3, 4,5, 6,7, 2,3, 4,5, 6,7, 4,5, 6,7, 6,7};
        int p = b % 20, z = b / 20;
        m0 = (long)PI[p] * MT;
        n0 = (long)PN[p] * NT;
        kbase = (long)z * sg.kc;
        C += (long)z * sg.pstride;
    } else {
        m0 = (long)(b >> 3) * MT;
        n0 = (long)(b & 7) * NT;
        kbase = 0;
    }
    const int niter = sg.kc / BKT;

    int acc0[2][4][4], accx[2][4][4];
#pragma unroll
    for (int i = 0; i < 2; ++i)
#pragma unroll
        for (int j = 0; j < 4; ++j)
#pragma unroll
            for (int q = 0; q < 4; ++q) { acc0[i][j][q] = 0; accx[i][j][q] = 0; }

    // prologue
    load_stage(base, sg.A0, sg.A1, sg.B0, sg.B1, sg.lda, sg.ldb, m0, n0, kbase, tid);

    for (int i = 0; i < niter; ++i) {
        if (i + 1 < niter) {
            // issue next stage first, then wait only for the current one
            load_stage(base + ((i + 1) & 1) * STAGE_B, sg.A0, sg.A1, sg.B0, sg.B1,
                       sg.lda, sg.ldb, m0, n0, kbase + (long)(i + 1) * BKT, tid);
            asm volatile("cp.async.wait_group 1;" ::: "memory");
        } else {
            asm volatile("cp.async.wait_group 0;" ::: "memory");
        }
        __syncthreads();

        const uint32_t sb = base + (i & 1) * STAGE_B;
        const uint32_t Ad0 = sb, Ad1 = sb + TILE_A;
        const uint32_t Bd0 = sb + 2 * TILE_A, Bd1 = sb + 2 * TILE_A + TILE_BB;

#pragma unroll
        for (int ks = 0; ks < 4; ++ks) {   // each ks = 32B = K32 int8
            uint32_t a0[2][4], a1[2][4], b0f[2][4], b1f[2][4];
            int ck = 2 * ks + hi4;
#pragma unroll
            for (int mt = 0; mt < 2; ++mt) {
                int row = wm * 32 + mt * 16 + r15;
                ldsm_x4(a0[mt], Ad0 + swz(row, ck));
                ldsm_x4(a1[mt], Ad1 + swz(row, ck));
            }
#pragma unroll
            for (int np = 0; np < 2; ++np) {
                int row = wn * 32 + np * 16 + r15;
                ldsm_x4(b0f[np], Bd0 + swz(row, ck));
                ldsm_x4(b1f[np], Bd1 + swz(row, ck));
            }
#pragma unroll
            for (int mt = 0; mt < 2; ++mt)
#pragma unroll
                for (int nt = 0; nt < 4; ++nt) {
                    int np = nt >> 1, p = nt & 1;
                    imma16832(acc0[mt][nt], a0[mt], b0f[np][p], b0f[np][p + 2]);
                    imma16832(accx[mt][nt], a0[mt], b1f[np][p], b1f[np][p + 2]);
                    imma16832(accx[mt][nt], a1[mt], b0f[np][p], b0f[np][p + 2]);
                }
        }
        __syncthreads();
    }

    // epilogue: dequantize and store fp32
#pragma unroll
    for (int mt = 0; mt < 2; ++mt) {
        long row = m0 + wm * 32 + mt * 16 + (lane >> 2);
#pragma unroll
        for (int nt = 0; nt < 4; ++nt) {
            long col = n0 + wn * 32 + nt * 8 + 2 * (lane & 3);
            float e0 = S2 * (float)acc0[mt][nt][0] + S2B * (float)accx[mt][nt][0];
            float e1 = S2 * (float)acc0[mt][nt][1] + S2B * (float)accx[mt][nt][1];
            float e2 = S2 * (float)acc0[mt][nt][2] + S2B * (float)accx[mt][nt][2];
            float e3 = S2 * (float)acc0[mt][nt][3] + S2B * (float)accx[mt][nt][3];
            *(float2*)&C[row * DD + col] = make_float2(e0, e1);
            *(float2*)&C[(row + 8) * DD + col] = make_float2(e2, e3);
        }
    }
}

// ------- fused prep: row-major digits AND transposed digits from one read -------
__global__ __launch_bounds__(256) void quant_both(const float* __restrict__ X,
                                                  int8_t* __restrict__ Dr0, int8_t* __restrict__ Dr1,
                                                  int8_t* __restrict__ Dt0, int8_t* __restrict__ Dt1,
                                                  long R, long C) {
    __shared__ float s[32][33];
    const int tx = threadIdx.x, ty = threadIdx.y;
    const long c0 = (long)blockIdx.x * 32, r0 = (long)blockIdx.y * 32;
#pragma unroll
    for (int i = 0; i < 4; ++i) {
        long row = r0 + ty + 8 * i;
        float v = X[row * C + c0 + tx];
        s[tx][ty + 8 * i] = v;
        int8_t d0, d1;
        quant2(v, d0, d1);
        long o = row * C + c0 + tx;
        Dr0[o] = d0;
        Dr1[o] = d1;
    }
    __syncthreads();
#pragma unroll
    for (int i = 0; i < 4; ++i) {
        float v = s[ty + 8 * i][tx];
        int8_t d0, d1;
        quant2(v, d0, d1);
        long o = (c0 + ty + 8 * i) * R + r0 + tx;
        Dt0[o] = d0;
        Dt1[o] = d1;
    }
}

// ------- combined W + Wr transposed digit split in one launch -------
__global__ __launch_bounds__(256) void quant_w2(const float* __restrict__ W0,
                                                const float* __restrict__ W1,
                                                int8_t* __restrict__ T00, int8_t* __restrict__ T01,
                                                int8_t* __restrict__ T10, int8_t* __restrict__ T11) {
    __shared__ float s[32][33];
    const int tx = threadIdx.x, ty = threadIdx.y;
    const long c0 = (long)blockIdx.x * 32, r0 = (long)blockIdx.y * 32;
    const float* X = blockIdx.z ? W1 : W0;
    int8_t* T0 = blockIdx.z ? T10 : T00;
    int8_t* T1 = blockIdx.z ? T11 : T01;
#pragma unroll
    for (int i = 0; i < 4; ++i)
        s[tx][ty + 8 * i] = X[(r0 + ty + 8 * i) * DD + c0 + tx];
    __syncthreads();
#pragma unroll
    for (int i = 0; i < 4; ++i) {
        float v = s[ty + 8 * i][tx];
        int8_t d0, d1;
        quant2(v, d0, d1);
        long o = (c0 + ty + 8 * i) * DD + r0 + tx;
        T0[o] = d0;
        T1[o] = d1;
    }
}

// ---------------- reduce split-K Gram partials (symmetric mirror, 128-granular) ----------------
__global__ void reduce_gram() {
    int idx = blockIdx.x * blockDim.x + threadIdx.x;
    int i = idx >> 9, j = idx & 511;
    size_t src = ((i >> 7) <= (j >> 7)) ? ((size_t)i * DD + j) : ((size_t)j * DD + i);
    float s = 0.f, p = 0.f;
#pragma unroll 8
    for (int z = 0; z < NSPLIT; ++z) {
        s += g_partS[(size_t)z * DD * DD + src];
        p += g_partP[(size_t)z * DD * DD + src];
    }
    g_GS[idx] = s;
    g_GP[idx] = p;
}

// ---------------- warp-per-row fused LN(rec) -> add stim -> relu -> LN(act) ----------------
__global__ __launch_bounds__(256) void ln_fuse(const float* __restrict__ rec,
                                               const float* __restrict__ stim,
                                               const float* __restrict__ grec,
                                               const float* __restrict__ brec,
                                               const float* __restrict__ gact,
                                               const float* __restrict__ bact,
                                               float* __restrict__ out) {
    const int lane = threadIdx.x & 31;
    const long row = (long)blockIdx.x * 8 + (threadIdx.x >> 5);
    const float* rr = rec + row * DD;
    const float* sr = stim + row * DD;
    float* orow = out + row * DD;

    float x[16];
    float a = 0.f, bsum = 0.f;
#pragma unroll
    for (int e = 0; e < 16; ++e) {
        x[e] = rr[e * 32 + lane];
        a += x[e];
        bsum += x[e] * x[e];
    }
#pragma unroll
    for (int o = 16; o; o >>= 1) {
        a += __shfl_xor_sync(0xffffffffu, a, o);
        bsum += __shfl_xor_sync(0xffffffffu, bsum, o);
    }
    float mu = a * (1.f / DD);
    float var = bsum * (1.f / DD) - mu * mu;
    float rstd = rsqrtf(var + 1e-5f);

    float v[16];
    a = 0.f; bsum = 0.f;
#pragma unroll
    for (int e = 0; e < 16; ++e) {
        int c = e * 32 + lane;
        float rn = (x[e] - mu) * rstd * grec[c] + brec[c];
        v[e] = fmaxf(sr[c] + rn, 0.f);
        a += v[e];
        bsum += v[e] * v[e];
    }
#pragma unroll
    for (int o = 16; o; o >>= 1) {
        a += __shfl_xor_sync(0xffffffffu, a, o);
        bsum += __shfl_xor_sync(0xffffffffu, bsum, o);
    }
    float mu2 = a * (1.f / DD);
    float var2 = bsum * (1.f / DD) - mu2 * mu2;
    float rstd2 = rsqrtf(var2 + 1e-5f);
#pragma unroll
    for (int e = 0; e < 16; ++e) {
        int c = e * 32 + lane;
        orow[c] = (v[e] - mu2) * rstd2 * gact[c] + bact[c];
    }
}

// ---------- weight update: out = l2norm_rows(W*(1-decay_i) + alpha_j*(G@W)), both mats ----------
#define RPC 8
__global__ __launch_bounds__(512) void weight_update(const float* __restrict__ W0,
                                                     const float* __restrict__ G0,
                                                     const float* __restrict__ W1,
                                                     const float* __restrict__ G1,
                                                     const float* __restrict__ alpha,
                                                     const float* __restrict__ decay,
                                                     float* __restrict__ out0,
                                                     float* __restrict__ out1) {
    const float* Wm = blockIdx.y ? W1 : W0;
    const float* G = blockIdx.y ? G1 : G0;
    float* outp = blockIdx.y ? out1 : out0;

    const int i0 = blockIdx.x * RPC;
    const int j = threadIdx.x;
    const int lane = j & 31;
    const int w = j >> 5;

    __shared__ float Gsm[RPC][DD];
    __shared__ float red[16];
    __shared__ float norms[RPC];

#pragma unroll
    for (int r = 0; r < RPC; ++r) Gsm[r][j] = G[(size_t)(i0 + r) * DD + j];
    __syncthreads();

    float acc[RPC];
#pragma unroll
    for (int r = 0; r < RPC; ++r) acc[r] = 0.f;

#pragma unroll 4
    for (int k = 0; k < DD; ++k) {
        float wv = Wm[(size_t)k * DD + j];
#pragma unroll
        for (int r = 0; r < RPC; ++r) acc[r] = fmaf(Gsm[r][k], wv, acc[r]);
    }

    float aj = alpha[j];
#pragma unroll
    for (int r = 0; r < RPC; ++r)
        acc[r] = Wm[(size_t)(i0 + r) * DD + j] * (1.f - decay[i0 + r]) + aj * acc[r];

    for (int r = 0; r < RPC; ++r) {
        float s = acc[r] * acc[r];
#pragma unroll
        for (int o = 16; o; o >>= 1) s += __shfl_xor_sync(0xffffffffu, s, o);
        if (lane == 0) red[w] = s;
        __syncthreads();
        if (j == 0) {
            float tsum = 0.f;
#pragma unroll
            for (int q = 0; q < 16; ++q) tsum += red[q];
            norms[r] = fmaxf(sqrtf(tsum), 1e-12f);
        }
        __syncthreads();
    }

#pragma unroll
    for (int r = 0; r < RPC; ++r)
        outp[(size_t)(i0 + r) * DD + j] = acc[r] / norms[r];
}

// ---------------- launch ----------------
extern "C" void kernel_launch(void* const* d_in, const int* in_sizes, int n_in,
                              void* d_out, int out_size) {
    const float* stim = (const float*)d_in[0];
    const float* prev = (const float*)d_in[1];
    const float* W    = (const float*)d_in[2];
    const float* Wr   = (const float*)d_in[3];
    const float* alpha = (const float*)d_in[4];
    const float* decay = (const float*)d_in[5];
    const float* gact = (const float*)d_in[6];
    const float* bact = (const float*)d_in[7];
    const float* grec = (const float*)d_in[8];
    const float* brec = (const float*)d_in[9];
    float* out = (float*)d_out;

    const long Brows = in_sizes[0] / DD;  // 32768

    int8_t *s0, *s1, *p0, *p1, *st0, *st1, *pt0, *pt1, *wt0, *wt1, *wrt0, *wrt1;
    float *stim_out, *rec_out, *partS, *partP, *GS, *GP;
    cudaGetSymbolAddress((void**)&s0, g_s0);
    cudaGetSymbolAddress((void**)&s1, g_s1);
    cudaGetSymbolAddress((void**)&p0, g_p0);
    cudaGetSymbolAddress((void**)&p1, g_p1);
    cudaGetSymbolAddress((void**)&st0, g_st0);
    cudaGetSymbolAddress((void**)&st1, g_st1);
    cudaGetSymbolAddress((void**)&pt0, g_pt0);
    cudaGetSymbolAddress((void**)&pt1, g_pt1);
    cudaGetSymbolAddress((void**)&wt0, g_wt0);
    cudaGetSymbolAddress((void**)&wt1, g_wt1);
    cudaGetSymbolAddress((void**)&wrt0, g_wrt0);
    cudaGetSymbolAddress((void**)&wrt1, g_wrt1);
    cudaGetSymbolAddress((void**)&stim_out, g_stim_out);
    cudaGetSymbolAddress((void**)&rec_out, g_rec_out);
    cudaGetSymbolAddress((void**)&partS, g_partS);
    cudaGetSymbolAddress((void**)&partP, g_partP);
    cudaGetSymbolAddress((void**)&GS, g_GS);
    cudaGetSymbolAddress((void**)&GP, g_GP);

    cudaFuncSetAttribute(mma_all, cudaFuncAttributeMaxDynamicSharedMemorySize, SMEM_DYN);

    // launches 0-2: quantization prep (mma_all stays at ncu capture index 3)
    dim3 tb(32, 8);
    quant_both<<<dim3(DD / 32, Brows / 32), tb>>>(stim, s0, s1, st0, st1, Brows, DD);
    quant_both<<<dim3(DD / 32, Brows / 32), tb>>>(prev, p0, p1, pt0, pt1, Brows, DD);
    quant_w2<<<dim3(DD / 32, DD / 32, 2), tb>>>(W, Wr, wt0, wt1, wrt0, wrt1);

    // launch 3: ALL four GEMMs merged, gram blocks first (LPT order)
    const int fwdBlocks = (int)(Brows / MT) * (DD / NT);  // 2048
    const int gramBlocks = 20 * NSPLIT;                   // 320
    const int kcg = (int)(Brows / NSPLIT);                // 2048
    Seg4 segs;
    segs.s[0] = {st0, st1, st0, st1, Brows, Brows, partS, (long)DD * DD, kcg, 1, 0};
    segs.s[1] = {pt0, pt1, pt0, pt1, Brows, Brows, partP, (long)DD * DD, kcg, 1, gramBlocks};
    segs.s[2] = {s0, s1, wt0, wt1, DD, DD, stim_out, 0, DD, 0, 2 * gramBlocks};
    segs.s[3] = {p0, p1, wrt0, wrt1, DD, DD, rec_out, 0, DD, 0, 2 * gramBlocks + fwdBlocks};
    mma_all<<<2 * gramBlocks + 2 * fwdBlocks, 256, SMEM_DYN>>>(segs);

    reduce_gram<<<(DD * DD) / 256, 256>>>();

    ln_fuse<<<(unsigned)(Brows / 8), 256>>>(rec_out, stim_out, grec, brec, gact, bact, out);

    size_t off = (size_t)Brows * DD;
    weight_update<<<dim3(DD / RPC, 2), 512>>>(W, GS, Wr, GP, alpha, decay,
                                              out + off, out + off + (size_t)DD * DD);
}

// round 8
// speedup vs baseline: 2.0827x; 2.0827x over previous
#include <cuda_runtime.h>
#include <cuda_bf16.h>
#include <cstdint>

typedef __nv_bfloat16 bf16;

// ---------------- problem constants ----------------
#define DD 512
#define MAXB 32768
#define NSPLIT 16
#define BKT 64                          // K per stage -> 128B rows
#define MT 128
#define NT 64
#define TILE_A (MT * BKT * 2)           // 16384 B
#define TILE_BB (NT * BKT * 2)          // 8192 B
#define STAGE_B (2 * TILE_A + 2 * TILE_BB)  // 49152 B
#define SMEM_DYN (2 * STAGE_B + 128)        // 98432 B -> 2 CTAs/SM

// ---------------- scratch (device globals; no allocation) ----------------
__device__ __align__(256) bf16 g_s_hi[(size_t)MAXB * DD];
__device__ __align__(256) bf16 g_s_lo[(size_t)MAXB * DD];
__device__ __align__(256) bf16 g_p_hi[(size_t)MAXB * DD];
__device__ __align__(256) bf16 g_p_lo[(size_t)MAXB * DD];
__device__ __align__(256) bf16 g_st_hi[(size_t)DD * MAXB];
__device__ __align__(256) bf16 g_st_lo[(size_t)DD * MAXB];
__device__ __align__(256) bf16 g_pt_hi[(size_t)DD * MAXB];
__device__ __align__(256) bf16 g_pt_lo[(size_t)DD * MAXB];
__device__ __align__(256) bf16 g_wt_hi[DD * DD];
__device__ __align__(256) bf16 g_wt_lo[DD * DD];
__device__ __align__(256) bf16 g_wrt_hi[DD * DD];
__device__ __align__(256) bf16 g_wrt_lo[DD * DD];
__device__ __align__(256) float g_stim_out[(size_t)MAXB * DD];
__device__ __align__(256) float g_rec_out[(size_t)MAXB * DD];
__device__ __align__(256) float g_partS[(size_t)NSPLIT * DD * DD];
__device__ __align__(256) float g_partP[(size_t)NSPLIT * DD * DD];
__device__ __align__(256) float g_GS[DD * DD];
__device__ __align__(256) float g_GP[DD * DD];

// ---------------- PTX helpers (base-ISA only: sm_80+ safe) ----------------
__device__ __forceinline__ uint32_t smem_u32(const void* p) {
    uint32_t a;
    asm("{ .reg .u64 t; cvta.to.shared.u64 t, %1; cvt.u32.u64 %0, t; }" : "=r"(a) : "l"(p));
    return a;
}
__device__ __forceinline__ void ldsm_x4(uint32_t* r, uint32_t addr) {
    asm volatile("ldmatrix.sync.aligned.m8n8.x4.shared.b16 {%0,%1,%2,%3}, [%4];"
                 : "=r"(r[0]), "=r"(r[1]), "=r"(r[2]), "=r"(r[3]) : "r"(addr));
}
__device__ __forceinline__ void mma16816(float* c, const uint32_t* a, uint32_t b0, uint32_t b1) {
    asm volatile(
        "mma.sync.aligned.m16n8k16.row.col.f32.bf16.bf16.f32 "
        "{%0,%1,%2,%3}, {%4,%5,%6,%7}, {%8,%9}, {%0,%1,%2,%3};"
        : "+f"(c[0]), "+f"(c[1]), "+f"(c[2]), "+f"(c[3])
        : "r"(a[0]), "r"(a[1]), "r"(a[2]), "r"(a[3]), "r"(b0), "r"(b1));
}
__device__ __forceinline__ void cp16(uint32_t dst, const void* src) {
    asm volatile("cp.async.cg.shared.global [%0], [%1], 16;" :: "r"(dst), "l"(src) : "memory");
}
#define CP_COMMIT() asm volatile("cp.async.commit_group;" ::: "memory")

// swizzled smem byte offset within a tile: 128B rows, 8 x 16B chunks, chunk xor (row&7)
__device__ __forceinline__ uint32_t swz(int row, int chunk) {
    return (uint32_t)(row * 128 + ((chunk ^ (row & 7)) << 4));
}

// ---------------- segment descriptor for the merged GEMM launch ----------------
struct Seg {
    const bf16 *Ah, *Al, *Bh, *Bl;
    long lda, ldb;
    float* C;
    long pstride;
    int kc;     // K per block
    int gram;   // 0: forward tiling, 1: upper-tri gram tiling
    int blk0;   // first global block id of this segment
};
struct Seg4 { Seg s[4]; };

// ---------------- stage loader: Ahi(128), Alo(128), Bhi(64), Blo(64) rows ----------------
__device__ __forceinline__ void load_stage(uint32_t sb,
                                           const bf16* __restrict__ Ahi, const bf16* __restrict__ Alo,
                                           const bf16* __restrict__ Bhi, const bf16* __restrict__ Blo,
                                           long lda, long ldb, long m0, long n0, long k0, int tid) {
    const bf16* pAh = Ahi + m0 * lda + k0;
    const bf16* pAl = Alo + m0 * lda + k0;
    const bf16* pBh = Bhi + n0 * ldb + k0;
    const bf16* pBl = Blo + n0 * ldb + k0;
#pragma unroll
    for (int q = 0; q < 4; ++q) {
        int ci = tid + q * 256;
        int row = ci >> 3, c = ci & 7;
        cp16(sb + swz(row, c), pAh + (long)row * lda + c * 8);
    }
#pragma unroll
    for (int q = 0; q < 4; ++q) {
        int ci = tid + q * 256;
        int row = ci >> 3, c = ci & 7;
        cp16(sb + TILE_A + swz(row, c), pAl + (long)row * lda + c * 8);
    }
#pragma unroll
    for (int q = 0; q < 2; ++q) {
        int ci = tid + q * 256;
        int row = ci >> 3, c = ci & 7;
        cp16(sb + 2 * TILE_A + swz(row, c), pBh + (long)row * ldb + c * 8);
    }
#pragma unroll
    for (int q = 0; q < 2; ++q) {
        int ci = tid + q * 256;
        int row = ci >> 3, c = ci & 7;
        cp16(sb + 2 * TILE_A + TILE_BB + swz(row, c), pBl + (long)row * ldb + c * 8);
    }
    CP_COMMIT();
}

// ---------------- merged mma.sync GEMM: all 4 GEMMs in one launch ----------------
__global__ __launch_bounds__(256, 2)
void mma_all(Seg4 segs) {
    extern __shared__ char smraw[];
    const uint32_t base = (smem_u32(smraw) + 127u) & ~127u;

    const int bid = blockIdx.x;
    int si = (bid >= segs.s[2].blk0) ? ((bid >= segs.s[3].blk0) ? 3 : 2)
                                     : ((bid >= segs.s[1].blk0) ? 1 : 0);
    const Seg sg = segs.s[si];
    const int b = bid - sg.blk0;

    const int tid = threadIdx.x;
    const int lane = tid & 31;
    const int wid = tid >> 5;
    const int wm = wid >> 1;       // 4 warp-rows of 32
    const int wn = wid & 1;        // 2 warp-cols of 32
    const int r15 = lane & 15;
    const int hi4 = lane >> 4;

    long m0, n0, kbase;
    float* C = sg.C;
    if (sg.gram) {
        // 20 upper-tri (128-granular) tiles of shape 128x64
        const int PI[20] = {0,0, 0,0, 0,0, 0,0, 1,1, 1,1, 1,1, 2,2, 2,2, 3,3};
        const int PN[20] = {0,1, 2,3, 4,5, 6,7, 2,3, 4,5, 6,7, 4,5, 6,7, 6,7};
        int p = b % 20, z = b / 20;
        m0 = (long)PI[p] * MT;
        n0 = (long)PN[p] * NT;
        kbase = (long)z * sg.kc;
        C += (long)z * sg.pstride;
    } else {
        m0 = (long)(b >> 3) * MT;
        n0 = (long)(b & 7) * NT;
        kbase = 0;
    }
    const int niter = sg.kc / BKT;

    float acc[2][4][4];
#pragma unroll
    for (int i = 0; i < 2; ++i)
#pragma unroll
        for (int j = 0; j < 4; ++j)
#pragma unroll
            for (int q = 0; q < 4; ++q) acc[i][j][q] = 0.f;

    // prologue: stage 0
    load_stage(base, sg.Ah, sg.Al, sg.Bh, sg.Bl, sg.lda, sg.ldb, m0, n0, kbase, tid);

    // single-barrier double-buffer mainloop:
    //   wait stage i -> barrier (also proves everyone is done reading buf((i-1)&1))
    //   -> issue load of stage i+1 into buf((i+1)&1) == buf((i-1)&1) -> compute stage i
    for (int i = 0; i < niter; ++i) {
        asm volatile("cp.async.wait_group 0;" ::: "memory");
        __syncthreads();

        if (i + 1 < niter)
            load_stage(base + ((i + 1) & 1) * STAGE_B, sg.Ah, sg.Al, sg.Bh, sg.Bl,
                       sg.lda, sg.ldb, m0, n0, kbase + (long)(i + 1) * BKT, tid);

        const uint32_t sb = base + (i & 1) * STAGE_B;
        const uint32_t Ah = sb, Al = sb + TILE_A;
        const uint32_t Bh = sb + 2 * TILE_A, Bl = sb + 2 * TILE_A + TILE_BB;

#pragma unroll
        for (int ks = 0; ks < 4; ++ks) {
            uint32_t ah[2][4], al[2][4], bh[2][4], bl[2][4];
            int ck = 2 * ks + hi4;
#pragma unroll
            for (int mt = 0; mt < 2; ++mt) {
                int row = wm * 32 + mt * 16 + r15;
                ldsm_x4(ah[mt], Ah + swz(row, ck));
                ldsm_x4(al[mt], Al + swz(row, ck));
            }
#pragma unroll
            for (int np = 0; np < 2; ++np) {
                int row = wn * 32 + np * 16 + r15;
                ldsm_x4(bh[np], Bh + swz(row, ck));
                ldsm_x4(bl[np], Bl + swz(row, ck));
            }
#pragma unroll
            for (int mt = 0; mt < 2; ++mt)
#pragma unroll
                for (int nt = 0; nt < 4; ++nt) {
                    int np = nt >> 1, p = nt & 1;
                    mma16816(acc[mt][nt], ah[mt], bh[np][p], bh[np][p + 2]);
                    mma16816(acc[mt][nt], ah[mt], bl[np][p], bl[np][p + 2]);
                    mma16816(acc[mt][nt], al[mt], bh[np][p], bh[np][p + 2]);
                }
        }
    }

    // epilogue: write fp32 directly from accumulators
#pragma unroll
    for (int mt = 0; mt < 2; ++mt) {
        long row = m0 + wm * 32 + mt * 16 + (lane >> 2);
#pragma unroll
        for (int nt = 0; nt < 4; ++nt) {
            long col = n0 + wn * 32 + nt * 8 + 2 * (lane & 3);
            *(float2*)&C[row * DD + col] = make_float2(acc[mt][nt][0], acc[mt][nt][1]);
            *(float2*)&C[(row + 8) * DD + col] = make_float2(acc[mt][nt][2], acc[mt][nt][3]);
        }
    }
}

// ------- fused prep: row-major hi/lo AND transposed hi/lo from one read -------
__global__ __launch_bounds__(256) void split_both(const float* __restrict__ X,
                                                  bf16* __restrict__ Hr, bf16* __restrict__ Lr,
                                                  bf16* __restrict__ Th, bf16* __restrict__ Tl,
                                                  long R, long C) {
    __shared__ float s[32][33];
    const int tx = threadIdx.x, ty = threadIdx.y;
    const long c0 = (long)blockIdx.x * 32, r0 = (long)blockIdx.y * 32;
#pragma unroll
    for (int i = 0; i < 4; ++i) {
        long row = r0 + ty + 8 * i;
        float v = X[row * C + c0 + tx];
        s[tx][ty + 8 * i] = v;
        bf16 hb = __float2bfloat16(v);
        long o = row * C + c0 + tx;
        Hr[o] = hb;
        Lr[o] = __float2bfloat16(v - __bfloat162float(hb));
    }
    __syncthreads();
#pragma unroll
    for (int i = 0; i < 4; ++i) {
        float v = s[ty + 8 * i][tx];
        bf16 hb = __float2bfloat16(v);
        long o = (c0 + ty + 8 * i) * R + r0 + tx;
        Th[o] = hb;
        Tl[o] = __float2bfloat16(v - __bfloat162float(hb));
    }
}

// ------- combined W + Wr transposed split in one launch (grid.z selects) -------
__global__ __launch_bounds__(256) void split_w2(const float* __restrict__ W0,
                                                const float* __restrict__ W1,
                                                bf16* __restrict__ Th0, bf16* __restrict__ Tl0,
                                                bf16* __restrict__ Th1, bf16* __restrict__ Tl1) {
    __shared__ float s[32][33];
    const int tx = threadIdx.x, ty = threadIdx.y;
    const long c0 = (long)blockIdx.x * 32, r0 = (long)blockIdx.y * 32;
    const float* X = blockIdx.z ? W1 : W0;
    bf16* Th = blockIdx.z ? Th1 : Th0;
    bf16* Tl = blockIdx.z ? Tl1 : Tl0;
#pragma unroll
    for (int i = 0; i < 4; ++i)
        s[tx][ty + 8 * i] = X[(r0 + ty + 8 * i) * DD + c0 + tx];
    __syncthreads();
#pragma unroll
    for (int i = 0; i < 4; ++i) {
        float v = s[ty + 8 * i][tx];
        bf16 hb = __float2bfloat16(v);
        long o = (c0 + ty + 8 * i) * DD + r0 + tx;
        Th[o] = hb;
        Tl[o] = __float2bfloat16(v - __bfloat162float(hb));
    }
}

// ---------------- reduce split-K Gram partials (symmetric mirror, 128-granular) ----------------
__global__ void reduce_gram() {
    int idx = blockIdx.x * blockDim.x + threadIdx.x;
    int i = idx >> 9, j = idx & 511;
    size_t src = ((i >> 7) <= (j >> 7)) ? ((size_t)i * DD + j) : ((size_t)j * DD + i);
    float s = 0.f, p = 0.f;
#pragma unroll 8
    for (int z = 0; z < NSPLIT; ++z) {
        s += g_partS[(size_t)z * DD * DD + src];
        p += g_partP[(size_t)z * DD * DD + src];
    }
    g_GS[idx] = s;
    g_GP[idx] = p;
}

// ---------------- warp-per-row fused LN(rec) -> add stim -> relu -> LN(act) ----------------
__global__ __launch_bounds__(256) void ln_fuse(const float* __restrict__ rec,
                                               const float* __restrict__ stim,
                                               const float* __restrict__ grec,
                                               const float* __restrict__ brec,
                                               const float* __restrict__ gact,
                                               const float* __restrict__ bact,
                                               float* __restrict__ out) {
    const int lane = threadIdx.x & 31;
    const long row = (long)blockIdx.x * 8 + (threadIdx.x >> 5);
    const float* rr = rec + row * DD;
    const float* sr = stim + row * DD;
    float* orow = out + row * DD;

    float x[16];
    float a = 0.f, bsum = 0.f;
#pragma unroll
    for (int e = 0; e < 16; ++e) {
        x[e] = rr[e * 32 + lane];
        a += x[e];
        bsum += x[e] * x[e];
    }
#pragma unroll
    for (int o = 16; o; o >>= 1) {
        a += __shfl_xor_sync(0xffffffffu, a, o);
        bsum += __shfl_xor_sync(0xffffffffu, bsum, o);
    }
    float mu = a * (1.f / DD);
    float var = bsum * (1.f / DD) - mu * mu;
    float rstd = rsqrtf(var + 1e-5f);

    float v[16];
    a = 0.f; bsum = 0.f;
#pragma unroll
    for (int e = 0; e < 16; ++e) {
        int c = e * 32 + lane;
        float rn = (x[e] - mu) * rstd * grec[c] + brec[c];
        v[e] = fmaxf(sr[c] + rn, 0.f);
        a += v[e];
        bsum += v[e] * v[e];
    }
#pragma unroll
    for (int o = 16; o; o >>= 1) {
        a += __shfl_xor_sync(0xffffffffu, a, o);
        bsum += __shfl_xor_sync(0xffffffffu, bsum, o);
    }
    float mu2 = a * (1.f / DD);
    float var2 = bsum * (1.f / DD) - mu2 * mu2;
    float rstd2 = rsqrtf(var2 + 1e-5f);
#pragma unroll
    for (int e = 0; e < 16; ++e) {
        int c = e * 32 + lane;
        orow[c] = (v[e] - mu2) * rstd2 * gact[c] + bact[c];
    }
}

// ---------- weight update: out = l2norm_rows(W*(1-decay_i) + alpha_j*(G@W)), both mats ----------
#define RPC 8
__global__ __launch_bounds__(512) void weight_update(const float* __restrict__ W0,
                                                     const float* __restrict__ G0,
                                                     const float* __restrict__ W1,
                                                     const float* __restrict__ G1,
                                                     const float* __restrict__ alpha,
                                                     const float* __restrict__ decay,
                                                     float* __restrict__ out0,
                                                     float* __restrict__ out1) {
    const float* Wm = blockIdx.y ? W1 : W0;
    const float* G = blockIdx.y ? G1 : G0;
    float* outp = blockIdx.y ? out1 : out0;

    const int i0 = blockIdx.x * RPC;
    const int j = threadIdx.x;
    const int lane = j & 31;
    const int w = j >> 5;

    __shared__ float Gsm[RPC][DD];
    __shared__ float red[16];
    __shared__ float norms[RPC];

#pragma unroll
    for (int r = 0; r < RPC; ++r) Gsm[r][j] = G[(size_t)(i0 + r) * DD + j];
    __syncthreads();

    float acc[RPC];
#pragma unroll
    for (int r = 0; r < RPC; ++r) acc[r] = 0.f;

#pragma unroll 4
    for (int k = 0; k < DD; ++k) {
        float wv = Wm[(size_t)k * DD + j];
#pragma unroll
        for (int r = 0; r < RPC; ++r) acc[r] = fmaf(Gsm[r][k], wv, acc[r]);
    }

    float aj = alpha[j];
#pragma unroll
    for (int r = 0; r < RPC; ++r)
        acc[r] = Wm[(size_t)(i0 + r) * DD + j] * (1.f - decay[i0 + r]) + aj * acc[r];

    for (int r = 0; r < RPC; ++r) {
        float s = acc[r] * acc[r];
#pragma unroll
        for (int o = 16; o; o >>= 1) s += __shfl_xor_sync(0xffffffffu, s, o);
        if (lane == 0) red[w] = s;
        __syncthreads();
        if (j == 0) {
            float tsum = 0.f;
#pragma unroll
            for (int q = 0; q < 16; ++q) tsum += red[q];
            norms[r] = fmaxf(sqrtf(tsum), 1e-12f);
        }
        __syncthreads();
    }

#pragma unroll
    for (int r = 0; r < RPC; ++r)
        outp[(size_t)(i0 + r) * DD + j] = acc[r] / norms[r];
}

// ---------------- launch ----------------
extern "C" void kernel_launch(void* const* d_in, const int* in_sizes, int n_in,
                              void* d_out, int out_size) {
    const float* stim = (const float*)d_in[0];
    const float* prev = (const float*)d_in[1];
    const float* W    = (const float*)d_in[2];
    const float* Wr   = (const float*)d_in[3];
    const float* alpha = (const float*)d_in[4];
    const float* decay = (const float*)d_in[5];
    const float* gact = (const float*)d_in[6];
    const float* bact = (const float*)d_in[7];
    const float* grec = (const float*)d_in[8];
    const float* brec = (const float*)d_in[9];
    float* out = (float*)d_out;

    const long Brows = in_sizes[0] / DD;  // 32768

    bf16 *s_hi, *s_lo, *p_hi, *p_lo, *st_hi, *st_lo, *pt_hi, *pt_lo;
    bf16 *wt_hi, *wt_lo, *wrt_hi, *wrt_lo;
    float *stim_out, *rec_out, *partS, *partP, *GS, *GP;
    cudaGetSymbolAddress((void**)&s_hi, g_s_hi);
    cudaGetSymbolAddress((void**)&s_lo, g_s_lo);
    cudaGetSymbolAddress((void**)&p_hi, g_p_hi);
    cudaGetSymbolAddress((void**)&p_lo, g_p_lo);
    cudaGetSymbolAddress((void**)&st_hi, g_st_hi);
    cudaGetSymbolAddress((void**)&st_lo, g_st_lo);
    cudaGetSymbolAddress((void**)&pt_hi, g_pt_hi);
    cudaGetSymbolAddress((void**)&pt_lo, g_pt_lo);
    cudaGetSymbolAddress((void**)&wt_hi, g_wt_hi);
    cudaGetSymbolAddress((void**)&wt_lo, g_wt_lo);
    cudaGetSymbolAddress((void**)&wrt_hi, g_wrt_hi);
    cudaGetSymbolAddress((void**)&wrt_lo, g_wrt_lo);
    cudaGetSymbolAddress((void**)&stim_out, g_stim_out);
    cudaGetSymbolAddress((void**)&rec_out, g_rec_out);
    cudaGetSymbolAddress((void**)&partS, g_partS);
    cudaGetSymbolAddress((void**)&partP, g_partP);
    cudaGetSymbolAddress((void**)&GS, g_GS);
    cudaGetSymbolAddress((void**)&GP, g_GP);

    cudaFuncSetAttribute(mma_all, cudaFuncAttributeMaxDynamicSharedMemorySize, SMEM_DYN);

    // launches 0-2: prep (mma_all stays at ncu capture index 3)
    dim3 tb(32, 8);
    split_both<<<dim3(DD / 32, Brows / 32), tb>>>(stim, s_hi, s_lo, st_hi, st_lo, Brows, DD);
    split_both<<<dim3(DD / 32, Brows / 32), tb>>>(prev, p_hi, p_lo, pt_hi, pt_lo, Brows, DD);
    split_w2<<<dim3(DD / 32, DD / 32, 2), tb>>>(W, Wr, wt_hi, wt_lo, wrt_hi, wrt_lo);

    // launch 3: ALL four GEMMs merged, gram blocks first (LPT order)
    const int fwdBlocks = (int)(Brows / MT) * (DD / NT);  // 2048
    const int gramBlocks = 20 * NSPLIT;                   // 320
    const int kcg = (int)(Brows / NSPLIT);                // 2048
    Seg4 segs;
    segs.s[0] = {st_hi, st_lo, st_hi, st_lo, Brows, Brows, partS, (long)DD * DD, kcg, 1, 0};
    segs.s[1] = {pt_hi, pt_lo, pt_hi, pt_lo, Brows, Brows, partP, (long)DD * DD, kcg, 1, gramBlocks};
    segs.s[2] = {s_hi, s_lo, wt_hi, wt_lo, DD, DD, stim_out, 0, DD, 0, 2 * gramBlocks};
    segs.s[3] = {p_hi, p_lo, wrt_hi, wrt_lo, DD, DD, rec_out, 0, DD, 0, 2 * gramBlocks + fwdBlocks};
    mma_all<<<2 * gramBlocks + 2 * fwdBlocks, 256, SMEM_DYN>>>(segs);

    reduce_gram<<<(DD * DD) / 256, 256>>>();

    ln_fuse<<<(unsigned)(Brows / 8), 256>>>(rec_out, stim_out, grec, brec, gact, bact, out);

    size_t off = (size_t)Brows * DD;
    weight_update<<<dim3(DD / RPC, 2), 512>>>(W, GS, Wr, GP, alpha, decay,
                                              out + off, out + off + (size_t)DD * DD);
}